// round 17
// baseline (speedup 1.0000x reference)
#include <cuda_runtime.h>

// out[(b*N+n)*D + c, s] = q[b, s, c] * w[n, c]
// q: (B=8, S=2048, D=256) fp32, c contiguous
// w: (N=20, D=256) fp32
// out: (B*N=160, D=256, S=2048) fp32, s contiguous
//
// R16 = R10 (best, 51.3us) with ONE change: plain .wb stores instead of
// __stcs. Single-variable A/B isolating the streaming-store hint, the only
// knob never tested alone. Everything else byte-identical to R10:
// NSPLIT=4 class split, STILE=64 smem transpose, launch_bounds(256,8).

#define BB 8
#define SS 2048
#define DD 256
#define NN 20
#define STILE 64
#define NSPLIT 4
#define NPB (NN / NSPLIT)   // 5 classes per block

__global__ __launch_bounds__(256, 8)
void FeatureReweightingModule_72447508349057_kernel(
    const float* __restrict__ q,
    const float* __restrict__ w,
    float* __restrict__ out)
{
    __shared__ float tile[STILE][33];   // [s_local][c_local], padded
    __shared__ float ws[NPB][32];       // weight slice (5 x 32 = 160 elems)

    const int s0 = blockIdx.x * STILE;          // 32 s-tiles
    const int c0 = blockIdx.y << 5;             // 8 c-tiles
    const int b  = blockIdx.z >> 2;             // 8 batches
    const int n0 = (blockIdx.z & 3) * NPB;      // class quarter: 0,5,10,15

    const int tid = threadIdx.x;                // 256 threads

    // Stage the 5x32 weight slice (160 <= 256 threads: single guarded store).
    if (tid < NPB * 32) {
        const int n = tid >> 5;
        const int c = tid & 31;
        ws[n][c] = w[(n0 + n) * DD + c0 + c];
    }

    // Load phase: 2 coalesced LDG.128 per thread along c.
    #pragma unroll
    for (int k = 0; k < 2; k++) {
        const int idx = tid + k * 256;
        const int sl  = idx >> 3;             // 0..63
        const int cq  = (idx & 7) << 2;       // 0,4,...,28
        const float4 v = *reinterpret_cast<const float4*>(
            &q[((size_t)b * SS + (s0 + sl)) * DD + c0 + cq]);
        tile[sl][cq + 0] = v.x;
        tile[sl][cq + 1] = v.y;
        tile[sl][cq + 2] = v.z;
        tile[sl][cq + 3] = v.w;
    }
    __syncthreads();

    // Transposed gather: two float4s of consecutive s for one c.
    // Banks (sq+i+cl) mod 32: all 32 distinct per warp -> conflict-free.
    const int cl = tid >> 3;                  // 0..31 (c within tile)
    const int sq = (tid & 7) << 2;            // 0,4,...,28
    float4 v0, v1;
    v0.x = tile[sq + 0][cl];
    v0.y = tile[sq + 1][cl];
    v0.z = tile[sq + 2][cl];
    v0.w = tile[sq + 3][cl];
    v1.x = tile[sq + 32][cl];
    v1.y = tile[sq + 33][cl];
    v1.z = tile[sq + 34][cl];
    v1.w = tile[sq + 35][cl];

    // Weights for this channel in registers: store loop is pure FMUL+STG.
    float wreg[NPB];
    #pragma unroll
    for (int n = 0; n < NPB; n++) wreg[n] = ws[n][cl];

    // Write phase: 10 independent STG.128 per thread (default .wb policy).
    float* orow = out + ((size_t)((b * NN + n0)) * DD + c0 + cl) * SS + (s0 + sq);
    #pragma unroll
    for (int n = 0; n < NPB; n++) {
        const float sc = wreg[n];
        float4 o0, o1;
        o0.x = v0.x * sc; o0.y = v0.y * sc; o0.z = v0.z * sc; o0.w = v0.w * sc;
        o1.x = v1.x * sc; o1.y = v1.y * sc; o1.z = v1.z * sc; o1.w = v1.w * sc;
        float* p = orow + (size_t)n * DD * SS;
        *reinterpret_cast<float4*>(p) = o0;
        *reinterpret_cast<float4*>(p + 32) = o1;
    }
}

extern "C" void kernel_launch(void* const* d_in, const int* in_sizes, int n_in,
                              void* d_out, int out_size)
{
    const float* q = (const float*)d_in[0];   // (8, 2048, 256) fp32
    const float* w = (const float*)d_in[1];   // (20, 256) fp32
    float* out = (float*)d_out;               // (160, 256, 2048) fp32

    dim3 grid(SS / STILE, DD / 32, BB * NSPLIT);   // (32, 8, 32) = 8192 blocks
    FeatureReweightingModule_72447508349057_kernel<<<grid, 256>>>(q, w, out);
}